// round 1
// baseline (speedup 1.0000x reference)
#include <cuda_runtime.h>
#include <math.h>

// Problem constants
#define TOK   4096      // B*N = 8*512
#define DIMC  1024
#define MLPC  4096
#define NSEQ  512
#define NHEAD 16
#define HD    64
#define PART  256
#define NBATCH 8

// ---------------- scratch (static device memory, no runtime alloc) ----------
__device__ float g_xn [TOK * DIMC];        // LN output (reused for LN1 and LN2)
__device__ float g_qkv[TOK * 3 * DIMC];    // fused qkv
__device__ float g_ctx[TOK * DIMC];        // attention context
__device__ float g_x1 [TOK * DIMC];        // post-attention residual stream
__device__ float g_h  [TOK * MLPC];        // gelu(fc1)

// ---------------- layernorm ----------------
__global__ void layernorm_k(const float* __restrict__ x,
                            const float* __restrict__ w,
                            const float* __restrict__ b,
                            float* __restrict__ out) {
    int row = blockIdx.x;
    int t = threadIdx.x;  // 256 threads, 4 floats each
    const float4* xr = reinterpret_cast<const float4*>(x + (size_t)row * DIMC);
    float4 v = xr[t];
    float s  = v.x + v.y + v.z + v.w;
    float sq = v.x*v.x + v.y*v.y + v.z*v.z + v.w*v.w;
    #pragma unroll
    for (int o = 16; o > 0; o >>= 1) {
        s  += __shfl_down_sync(0xffffffffu, s,  o);
        sq += __shfl_down_sync(0xffffffffu, sq, o);
    }
    __shared__ float ss[8], sq2[8];
    __shared__ float mean_s, rstd_s;
    int lane = t & 31, wp = t >> 5;
    if (lane == 0) { ss[wp] = s; sq2[wp] = sq; }
    __syncthreads();
    if (t == 0) {
        float S = 0.f, Q = 0.f;
        #pragma unroll
        for (int i = 0; i < 8; i++) { S += ss[i]; Q += sq2[i]; }
        float m = S * (1.0f / DIMC);
        float var = Q * (1.0f / DIMC) - m * m;
        mean_s = m;
        rstd_s = rsqrtf(var + 1e-5f);
    }
    __syncthreads();
    float m = mean_s, r = rstd_s;
    float4 wv = reinterpret_cast<const float4*>(w)[t];
    float4 bv = reinterpret_cast<const float4*>(b)[t];
    float4 o;
    o.x = (v.x - m) * r * wv.x + bv.x;
    o.y = (v.y - m) * r * wv.y + bv.y;
    o.z = (v.z - m) * r * wv.z + bv.z;
    o.w = (v.w - m) * r * wv.w + bv.w;
    reinterpret_cast<float4*>(out + (size_t)row * DIMC)[t] = o;
}

// ---------------- generic 128x128x8 SGEMM (NN), fused epilogue ----------------
__device__ __forceinline__ float gelu_f(float v) {
    return 0.5f * v * (1.0f + erff(v * 0.70710678118654752f));
}

// GELU: 0 = none, 1 = exact gelu after bias
// indices != nullptr : per-128-row-block expert weight/bias indirection
template<int GELU>
__global__ void sgemm128(const float* __restrict__ A, int lda,
                         const float* __restrict__ B, int ldb,
                         float* __restrict__ C, int ldc, int K,
                         const float* __restrict__ bias,
                         const float* __restrict__ res, int ldr,
                         const int* __restrict__ indices,
                         size_t wstride, int bstride) {
    if (indices) {
        int batch = (blockIdx.y * 128) / NSEQ;
        int idx = indices[batch];
        B    += (size_t)idx * wstride;
        bias += (size_t)idx * bstride;
    }
    __shared__ __align__(16) float As[8][128];
    __shared__ __align__(16) float Bs[8][128];
    int tid = threadIdx.x;           // 256
    int tx = tid & 15, ty = tid >> 4;
    int brow = blockIdx.y * 128, bcol = blockIdx.x * 128;
    int ar_ = tid >> 1, ac_ = (tid & 1) * 4;   // A tile: 128 rows x 8 k
    int br_ = tid >> 5, bc_ = (tid & 31) * 4;  // B tile: 8 k x 128 cols
    const float* Ap = A + (size_t)(brow + ar_) * lda + ac_;
    const float* Bp = B + (size_t)br_ * ldb + bcol + bc_;

    float acc[8][8];
    #pragma unroll
    for (int i = 0; i < 8; i++)
        #pragma unroll
        for (int j = 0; j < 8; j++) acc[i][j] = 0.f;

    for (int k0 = 0; k0 < K; k0 += 8) {
        float4 av = *reinterpret_cast<const float4*>(Ap + k0);
        As[ac_ + 0][ar_] = av.x;
        As[ac_ + 1][ar_] = av.y;
        As[ac_ + 2][ar_] = av.z;
        As[ac_ + 3][ar_] = av.w;
        float4 bv = *reinterpret_cast<const float4*>(Bp + (size_t)k0 * ldb);
        *reinterpret_cast<float4*>(&Bs[br_][bc_]) = bv;
        __syncthreads();
        #pragma unroll
        for (int k = 0; k < 8; k++) {
            float4 a0 = *reinterpret_cast<float4*>(&As[k][ty * 8]);
            float4 a1 = *reinterpret_cast<float4*>(&As[k][ty * 8 + 4]);
            float4 b0 = *reinterpret_cast<float4*>(&Bs[k][tx * 8]);
            float4 b1 = *reinterpret_cast<float4*>(&Bs[k][tx * 8 + 4]);
            float ar[8] = {a0.x, a0.y, a0.z, a0.w, a1.x, a1.y, a1.z, a1.w};
            float br[8] = {b0.x, b0.y, b0.z, b0.w, b1.x, b1.y, b1.z, b1.w};
            #pragma unroll
            for (int i = 0; i < 8; i++)
                #pragma unroll
                for (int j = 0; j < 8; j++) acc[i][j] += ar[i] * br[j];
        }
        __syncthreads();
    }
    #pragma unroll
    for (int i = 0; i < 8; i++) {
        int row = brow + ty * 8 + i;
        #pragma unroll
        for (int j = 0; j < 8; j++) {
            int col = bcol + tx * 8 + j;
            float v = acc[i][j];
            if (bias) v += bias[col];
            if (GELU) v = gelu_f(v);
            if (res) v += res[(size_t)row * ldr + col];
            C[(size_t)row * ldc + col] = v;
        }
    }
}

// ---------------- batched attention scores: attn_raw = (Q K^T) / 32 ----------
// per (b,h): Q [512,64] (lda 3072), K [512,64] (ldb 3072), C [512,512]
__global__ void attn_scores_k(const float* __restrict__ qkv,
                              float* __restrict__ attn) {
    int bh = blockIdx.z;
    int b = bh >> 4, h = bh & 15;
    const float* Q  = qkv + (size_t)b * NSEQ * 3 * DIMC + h * HD;
    const float* Kp = Q + DIMC;
    float* C = attn + (size_t)bh * NSEQ * NSEQ;

    __shared__ __align__(16) float As[8][128];
    __shared__ __align__(16) float Bs[8][128];
    int tid = threadIdx.x;
    int tx = tid & 15, ty = tid >> 4;
    int brow = blockIdx.y * 128, bcol = blockIdx.x * 128;
    int lr = tid >> 1, lc = (tid & 1) * 4;

    float acc[8][8];
    #pragma unroll
    for (int i = 0; i < 8; i++)
        #pragma unroll
        for (int j = 0; j < 8; j++) acc[i][j] = 0.f;

    for (int k0 = 0; k0 < HD; k0 += 8) {
        float4 av = *reinterpret_cast<const float4*>(Q + (size_t)(brow + lr) * (3 * DIMC) + k0 + lc);
        As[lc + 0][lr] = av.x; As[lc + 1][lr] = av.y;
        As[lc + 2][lr] = av.z; As[lc + 3][lr] = av.w;
        float4 bv = *reinterpret_cast<const float4*>(Kp + (size_t)(bcol + lr) * (3 * DIMC) + k0 + lc);
        Bs[lc + 0][lr] = bv.x; Bs[lc + 1][lr] = bv.y;
        Bs[lc + 2][lr] = bv.z; Bs[lc + 3][lr] = bv.w;
        __syncthreads();
        #pragma unroll
        for (int k = 0; k < 8; k++) {
            float4 a0 = *reinterpret_cast<float4*>(&As[k][ty * 8]);
            float4 a1 = *reinterpret_cast<float4*>(&As[k][ty * 8 + 4]);
            float4 b0 = *reinterpret_cast<float4*>(&Bs[k][tx * 8]);
            float4 b1 = *reinterpret_cast<float4*>(&Bs[k][tx * 8 + 4]);
            float ar[8] = {a0.x, a0.y, a0.z, a0.w, a1.x, a1.y, a1.z, a1.w};
            float br[8] = {b0.x, b0.y, b0.z, b0.w, b1.x, b1.y, b1.z, b1.w};
            #pragma unroll
            for (int i = 0; i < 8; i++)
                #pragma unroll
                for (int j = 0; j < 8; j++) acc[i][j] += ar[i] * br[j];
        }
        __syncthreads();
    }
    const float scale = 0.03125f;  // DIM^-0.5 = 1/32
    #pragma unroll
    for (int i = 0; i < 8; i++) {
        int row = brow + ty * 8 + i;
        #pragma unroll
        for (int j = 0; j < 8; j++) {
            int col = bcol + tx * 8 + j;
            C[(size_t)row * NSEQ + col] = acc[i][j] * scale;
        }
    }
}

// ---------------- in-place row softmax over 512 elements ----------------
__global__ void softmax_k(float* __restrict__ attn) {
    size_t row = blockIdx.x;
    float4* p = reinterpret_cast<float4*>(attn + row * NSEQ);
    int t = threadIdx.x;  // 128 threads * 4
    float4 v = p[t];
    float m = fmaxf(fmaxf(v.x, v.y), fmaxf(v.z, v.w));
    #pragma unroll
    for (int o = 16; o > 0; o >>= 1) m = fmaxf(m, __shfl_xor_sync(0xffffffffu, m, o));
    __shared__ float sm[4], ssum[4];
    int lane = t & 31, wp = t >> 5;
    if (lane == 0) sm[wp] = m;
    __syncthreads();
    m = fmaxf(fmaxf(sm[0], sm[1]), fmaxf(sm[2], sm[3]));
    float4 e;
    e.x = expf(v.x - m); e.y = expf(v.y - m);
    e.z = expf(v.z - m); e.w = expf(v.w - m);
    float s = e.x + e.y + e.z + e.w;
    #pragma unroll
    for (int o = 16; o > 0; o >>= 1) s += __shfl_xor_sync(0xffffffffu, s, o);
    if (lane == 0) ssum[wp] = s;
    __syncthreads();
    s = ssum[0] + ssum[1] + ssum[2] + ssum[3];
    float inv = 1.0f / s;
    e.x *= inv; e.y *= inv; e.z *= inv; e.w *= inv;
    p[t] = e;
}

// ---------------- batched attn @ V : ctx[b, i, h*64+d] ----------------
// per (b,h): A = attn [512,512], B = V [512,64] (ldb 3072), C [512,64] (ldc 1024)
__global__ void attn_v_k(const float* __restrict__ attn,
                         const float* __restrict__ qkv,
                         float* __restrict__ ctx) {
    int bh = blockIdx.z;
    int b = bh >> 4, h = bh & 15;
    const float* A = attn + (size_t)bh * NSEQ * NSEQ;
    const float* V = qkv + (size_t)b * NSEQ * 3 * DIMC + 2 * DIMC + h * HD;
    float* C = ctx + (size_t)b * NSEQ * DIMC + h * HD;

    __shared__ __align__(16) float As[8][128];
    __shared__ __align__(16) float Bs[8][64];
    int tid = threadIdx.x;
    int tx = tid & 15, ty = tid >> 4;   // 128 rows x 64 cols; 8x4 per thread
    int brow = blockIdx.y * 128;
    int ar_ = tid >> 1, ac_ = (tid & 1) * 4;
    int br_ = tid >> 5, bc_ = (tid & 31) * 2;

    float acc[8][4];
    #pragma unroll
    for (int i = 0; i < 8; i++)
        #pragma unroll
        for (int j = 0; j < 4; j++) acc[i][j] = 0.f;

    for (int k0 = 0; k0 < NSEQ; k0 += 8) {
        float4 av = *reinterpret_cast<const float4*>(A + (size_t)(brow + ar_) * NSEQ + k0 + ac_);
        As[ac_ + 0][ar_] = av.x; As[ac_ + 1][ar_] = av.y;
        As[ac_ + 2][ar_] = av.z; As[ac_ + 3][ar_] = av.w;
        float2 bv = *reinterpret_cast<const float2*>(V + (size_t)(k0 + br_) * (3 * DIMC) + bc_);
        Bs[br_][bc_ + 0] = bv.x;
        Bs[br_][bc_ + 1] = bv.y;
        __syncthreads();
        #pragma unroll
        for (int k = 0; k < 8; k++) {
            float4 a0 = *reinterpret_cast<float4*>(&As[k][ty * 8]);
            float4 a1 = *reinterpret_cast<float4*>(&As[k][ty * 8 + 4]);
            float4 b0 = *reinterpret_cast<float4*>(&Bs[k][tx * 4]);
            float ar[8] = {a0.x, a0.y, a0.z, a0.w, a1.x, a1.y, a1.z, a1.w};
            float br[4] = {b0.x, b0.y, b0.z, b0.w};
            #pragma unroll
            for (int i = 0; i < 8; i++)
                #pragma unroll
                for (int j = 0; j < 4; j++) acc[i][j] += ar[i] * br[j];
        }
        __syncthreads();
    }
    #pragma unroll
    for (int i = 0; i < 8; i++) {
        int row = brow + ty * 8 + i;
        #pragma unroll
        for (int j = 0; j < 4; j++) {
            C[(size_t)row * DIMC + tx * 4 + j] = acc[i][j];
        }
    }
}

// ---------------- launch ----------------
extern "C" void kernel_launch(void* const* d_in, const int* in_sizes, int n_in,
                              void* d_out, int out_size) {
    const float* x      = (const float*)d_in[0];
    const int*   indices= (const int*)  d_in[1];
    const float* ln1_w  = (const float*)d_in[2];
    const float* ln1_b  = (const float*)d_in[3];
    const float* qkv_w  = (const float*)d_in[4];
    const float* qkv_b  = (const float*)d_in[5];
    const float* out_w  = (const float*)d_in[6];
    const float* out_b  = (const float*)d_in[7];
    const float* ln2_w  = (const float*)d_in[8];
    const float* ln2_b  = (const float*)d_in[9];
    const float* fc1_w  = (const float*)d_in[10];
    const float* fc1_b  = (const float*)d_in[11];
    const float* fc2_w  = (const float*)d_in[12];
    const float* fc2_b  = (const float*)d_in[13];
    const float* exp_w  = (const float*)d_in[14];
    const float* exp_b  = (const float*)d_in[15];

    float* out_final = (float*)d_out;                       // [8,512,1024]
    float* attn      = out_final + (size_t)TOK * DIMC;      // [8,16,512,512]

    void* p;
    cudaGetSymbolAddress(&p, g_xn);  float* xn  = (float*)p;
    cudaGetSymbolAddress(&p, g_qkv); float* qkv = (float*)p;
    cudaGetSymbolAddress(&p, g_ctx); float* ctx = (float*)p;
    cudaGetSymbolAddress(&p, g_x1);  float* x1  = (float*)p;
    cudaGetSymbolAddress(&p, g_h);   float* h   = (float*)p;

    // LN1
    layernorm_k<<<TOK, 256>>>(x, ln1_w, ln1_b, xn);
    // QKV: [4096,1024] @ [1024,3072]
    sgemm128<0><<<dim3(24, 32), 256>>>(xn, DIMC, qkv_w, 3 * DIMC,
                                       qkv, 3 * DIMC, DIMC,
                                       qkv_b, nullptr, 0, nullptr, 0, 0);
    // scores -> attn output region (scaled)
    attn_scores_k<<<dim3(4, 4, NBATCH * NHEAD), 256>>>(qkv, attn);
    // softmax in place
    softmax_k<<<NBATCH * NHEAD * NSEQ, 128>>>(attn);
    // attn @ V -> ctx
    attn_v_k<<<dim3(1, 4, NBATCH * NHEAD), 256>>>(attn, qkv, ctx);
    // out proj + residual(x): [4096,1024] @ [1024,1024]
    sgemm128<0><<<dim3(8, 32), 256>>>(ctx, DIMC, out_w, DIMC,
                                      x1, DIMC, DIMC,
                                      out_b, x, DIMC, nullptr, 0, 0);
    // LN2
    layernorm_k<<<TOK, 256>>>(x1, ln2_w, ln2_b, xn);
    // fc1 + exact GELU: [4096,1024] @ [1024,4096]
    sgemm128<1><<<dim3(32, 32), 256>>>(xn, DIMC, fc1_w, MLPC,
                                       h, MLPC, DIMC,
                                       fc1_b, nullptr, 0, nullptr, 0, 0);
    // fc2 + residual -> out_final[:, 0:768]
    sgemm128<0><<<dim3(6, 32), 256>>>(h, MLPC, fc2_w, DIMC - PART,
                                      out_final, DIMC, MLPC,
                                      fc2_b, x1, DIMC, nullptr, 0, 0);
    // expert (per-batch weights) + residual -> out_final[:, 768:1024]
    sgemm128<0><<<dim3(2, 32), 256>>>(h, MLPC, exp_w, PART,
                                      out_final + (DIMC - PART), DIMC, MLPC,
                                      exp_b, x1 + (DIMC - PART), DIMC,
                                      indices, (size_t)MLPC * PART, PART);
}

// round 4
// speedup vs baseline: 5.2783x; 5.2783x over previous
#include <cuda_runtime.h>
#include <cuda_fp16.h>
#include <cuda_pipeline.h>
#include <mma.h>
#include <math.h>

#define TOK   4096
#define DIMC  1024
#define MLPC  4096
#define NSEQ  512
#define HD    64
#define PART  256

#define F_BIAS  1
#define F_GELU  2
#define F_RES   4
#define F_SCALE 8
#define F_OUTF  16
#define F_OUTH  32
#define F_IDX   64

using namespace nvcuda;

/* static device scratch */
__device__ __half g_xn_h [TOK * DIMC];
__device__ __half g_qkv_h[TOK * 3 * DIMC];
__device__ __half g_attn_h[(size_t)128 * NSEQ * NSEQ];
__device__ __half g_ctx_h[TOK * DIMC];
__device__ float  g_x1   [TOK * DIMC];
__device__ __half g_h_h  [TOK * MLPC];
__device__ __half g_qkvw_h[DIMC * 3 * DIMC];
__device__ __half g_outw_h[DIMC * DIMC];
__device__ __half g_fc1w_h[DIMC * MLPC];
__device__ __half g_fc2w_h[MLPC * (DIMC - PART)];
__device__ __half g_expw_h[8 * MLPC * PART];

__device__ __forceinline__ float gelu_f(float v) {
    return 0.5f * v * (1.0f + erff(v * 0.70710678118654752f));
}

/* fp32 to fp16 conversion */
__global__ void cvt_k(const float* __restrict__ in, __half* __restrict__ out, int n4) {
    int i = blockIdx.x * blockDim.x + threadIdx.x;
    if (i < n4) {
        float4 v = reinterpret_cast<const float4*>(in)[i];
        reinterpret_cast<__half2*>(out)[i * 2 + 0] = __floats2half2_rn(v.x, v.y);
        reinterpret_cast<__half2*>(out)[i * 2 + 1] = __floats2half2_rn(v.z, v.w);
    }
}

/* layernorm fp32 in, fp16 out */
__global__ void layernorm_h_k(const float* __restrict__ x,
                              const float* __restrict__ w,
                              const float* __restrict__ b,
                              __half* __restrict__ out) {
    int row = blockIdx.x;
    int t = threadIdx.x;
    float4 v = reinterpret_cast<const float4*>(x + (size_t)row * DIMC)[t];
    float s  = v.x + v.y + v.z + v.w;
    float sq = v.x * v.x + v.y * v.y + v.z * v.z + v.w * v.w;
    #pragma unroll
    for (int o = 16; o > 0; o >>= 1) {
        s  += __shfl_down_sync(0xffffffffu, s,  o);
        sq += __shfl_down_sync(0xffffffffu, sq, o);
    }
    __shared__ float ss[8];
    __shared__ float sq2[8];
    __shared__ float mean_s;
    __shared__ float rstd_s;
    int lane = t & 31;
    int wp = t >> 5;
    if (lane == 0) { ss[wp] = s; sq2[wp] = sq; }
    __syncthreads();
    if (t == 0) {
        float S = 0.f;
        float Q = 0.f;
        #pragma unroll
        for (int i = 0; i < 8; i++) { S += ss[i]; Q += sq2[i]; }
        float m = S * (1.0f / DIMC);
        mean_s = m;
        rstd_s = rsqrtf(Q * (1.0f / DIMC) - m * m + 1e-5f);
    }
    __syncthreads();
    float m = mean_s;
    float r = rstd_s;
    float4 wv = reinterpret_cast<const float4*>(w)[t];
    float4 bv = reinterpret_cast<const float4*>(b)[t];
    float o0 = (v.x - m) * r * wv.x + bv.x;
    float o1 = (v.y - m) * r * wv.y + bv.y;
    float o2 = (v.z - m) * r * wv.z + bv.z;
    float o3 = (v.w - m) * r * wv.w + bv.w;
    __half2* op = reinterpret_cast<__half2*>(out + (size_t)row * DIMC);
    op[t * 2 + 0] = __floats2half2_rn(o0, o1);
    op[t * 2 + 1] = __floats2half2_rn(o2, o3);
}

/* softmax: fp32 in-place plus fp16 copy */
__global__ void softmax_k(float* __restrict__ attn, __half* __restrict__ attn_h) {
    size_t row = blockIdx.x;
    float4* p = reinterpret_cast<float4*>(attn + row * NSEQ);
    int t = threadIdx.x;
    float4 v = p[t];
    float m = fmaxf(fmaxf(v.x, v.y), fmaxf(v.z, v.w));
    #pragma unroll
    for (int o = 16; o > 0; o >>= 1) m = fmaxf(m, __shfl_xor_sync(0xffffffffu, m, o));
    __shared__ float sm[4];
    __shared__ float ssum[4];
    int lane = t & 31;
    int wp = t >> 5;
    if (lane == 0) sm[wp] = m;
    __syncthreads();
    m = fmaxf(fmaxf(sm[0], sm[1]), fmaxf(sm[2], sm[3]));
    float4 e;
    e.x = expf(v.x - m);
    e.y = expf(v.y - m);
    e.z = expf(v.z - m);
    e.w = expf(v.w - m);
    float s = e.x + e.y + e.z + e.w;
    #pragma unroll
    for (int o = 16; o > 0; o >>= 1) s += __shfl_xor_sync(0xffffffffu, s, o);
    if (lane == 0) ssum[wp] = s;
    __syncthreads();
    s = ssum[0] + ssum[1] + ssum[2] + ssum[3];
    float inv = 1.0f / s;
    e.x *= inv;
    e.y *= inv;
    e.z *= inv;
    e.w *= inv;
    p[t] = e;
    __half2* hp = reinterpret_cast<__half2*>(attn_h + row * NSEQ);
    hp[t * 2 + 0] = __floats2half2_rn(e.x, e.y);
    hp[t * 2 + 1] = __floats2half2_rn(e.z, e.w);
}

/*
 * WMMA tensor-core GEMM. Block tile 128 x BN, K-step 32, double-buffered
 * shared tiles loaded with the pipeline API. 8 warps as 4(m) x 2(n):
 * each warp owns 32 x BN/2. BT=1 means B is [N,K] row-major (C = A by B-T).
 * Batched over blockIdx.z decomposed as (z>>4, z&15) with explicit strides.
 */
template<int BN, int FLAGS, int BT>
__global__ __launch_bounds__(256, 2)
void hgemm(const __half* __restrict__ A, int lda,
           const __half* __restrict__ B, int ldb,
           float* __restrict__ Cf, __half* __restrict__ Ch, int ldc,
           int K,
           const float* __restrict__ bias,
           const float* __restrict__ res, int ldr,
           float scale,
           const int* __restrict__ indices, long wstride, int bstride,
           long za1, long za2, long zb1, long zb2, long zc1, long zc2)
{
    const int z = blockIdx.z;
    const int zb = z >> 4;
    const int zh = z & 15;
    A += (long)zb * za1 + (long)zh * za2;
    B += (long)zb * zb1 + (long)zh * zb2;
    const long coff = (long)zb * zc1 + (long)zh * zc2;
    if (FLAGS & F_IDX) {
        int idx = indices[blockIdx.y >> 2];
        B    += (long)idx * wstride;
        bias += (long)idx * bstride;
    }
    const int brow = blockIdx.y * 128;
    const int bcol = blockIdx.x * BN;

    constexpr int AP  = 40;                 /* A smem pitch in halves */
    constexpr int BPN = BN + 8;             /* B pitch, NN layout */
    constexpr int BPT = 40;                 /* B pitch, NT layout */
    constexpr int ASZ = 128 * AP;           /* halves per A stage */
    constexpr int BSZ = BT ? (BN * BPT) : (32 * BPN);
    constexpr int TOTH = 2 * ASZ + 2 * BSZ;

    __shared__ __align__(16) __half smem[TOTH];
    __half* As = smem;
    __half* Bs = smem + 2 * ASZ;

    const int tid  = threadIdx.x;
    const int warp = tid >> 5;
    const int lane = tid & 31;
    const int wm = warp & 3;                /* 4 warp rows of 32 */
    const int wn = warp >> 2;               /* 2 warp cols of BN/2 */
    constexpr int NTF = BN / 32;            /* 16-wide frags per warp col */

    wmma::fragment<wmma::accumulator, 16, 16, 16, float> acc[2][NTF];
    #pragma unroll
    for (int i = 0; i < 2; i++) {
        #pragma unroll
        for (int j = 0; j < NTF; j++) wmma::fill_fragment(acc[i][j], 0.0f);
    }

    const int iters = K >> 5;

    /* per-thread load coords: A tile and NT B tile use row=tid/2, col 16-half chunk */
    const int lr = tid >> 1;
    const int lc = (tid & 1) * 16;

    /* preload stage 0 */
    {
        const __half* ga = A + (long)(brow + lr) * lda + lc;
        __pipeline_memcpy_async(&As[lr * AP + lc], ga, 16);
        __pipeline_memcpy_async(&As[lr * AP + lc + 8], ga + 8, 16);
        if (BT) {
            const __half* gb = B + (long)(bcol + lr) * ldb + lc;
            if (lr < BN) {
                __pipeline_memcpy_async(&Bs[lr * BPT + lc], gb, 16);
                __pipeline_memcpy_async(&Bs[lr * BPT + lc + 8], gb + 8, 16);
            }
        } else {
            constexpr int CH = BN / 8;
            #pragma unroll
            for (int q = 0; q < (32 * CH + 255) / 256; q++) {
                const int idx = tid + q * 256;
                if (idx < 32 * CH) {
                    const int r = idx / CH;
                    const int c = idx % CH;
                    __pipeline_memcpy_async(&Bs[r * BPN + c * 8],
                                            B + (long)r * ldb + bcol + c * 8, 16);
                }
            }
        }
        __pipeline_commit();
    }

    for (int it = 0; it < iters; ++it) {
        const int buf = it & 1;
        if (it + 1 < iters) {
            const int nbuf = (it + 1) & 1;
            const int nk = (it + 1) * 32;
            const __half* ga = A + (long)(brow + lr) * lda + nk + lc;
            __pipeline_memcpy_async(&As[nbuf * ASZ + lr * AP + lc], ga, 16);
            __pipeline_memcpy_async(&As[nbuf * ASZ + lr * AP + lc + 8], ga + 8, 16);
            if (BT) {
                const __half* gb = B + (long)(bcol + lr) * ldb + nk + lc;
                if (lr < BN) {
                    __pipeline_memcpy_async(&Bs[nbuf * BSZ + lr * BPT + lc], gb, 16);
                    __pipeline_memcpy_async(&Bs[nbuf * BSZ + lr * BPT + lc + 8], gb + 8, 16);
                }
            } else {
                constexpr int CH = BN / 8;
                #pragma unroll
                for (int q = 0; q < (32 * CH + 255) / 256; q++) {
                    const int idx = tid + q * 256;
                    if (idx < 32 * CH) {
                        const int r = idx / CH;
                        const int c = idx % CH;
                        __pipeline_memcpy_async(&Bs[nbuf * BSZ + r * BPN + c * 8],
                                                B + (long)(nk + r) * ldb + bcol + c * 8, 16);
                    }
                }
            }
            __pipeline_commit();
            __pipeline_wait_prior(1);
        } else {
            __pipeline_wait_prior(0);
        }
        __syncthreads();

        #pragma unroll
        for (int ks = 0; ks < 32; ks += 16) {
            wmma::fragment<wmma::matrix_a, 16, 16, 16, __half, wmma::row_major> af[2];
            #pragma unroll
            for (int mt = 0; mt < 2; mt++) {
                const __half* ap = &As[buf * ASZ + (wm * 32 + mt * 16) * AP + ks];
                wmma::load_matrix_sync(af[mt], ap, AP);
            }
            if (BT) {
                wmma::fragment<wmma::matrix_b, 16, 16, 16, __half, wmma::col_major> bf[NTF];
                #pragma unroll
                for (int nt = 0; nt < NTF; nt++) {
                    const __half* bp = &Bs[buf * BSZ + (wn * (BN / 2) + nt * 16) * BPT + ks];
                    wmma::load_matrix_sync(bf[nt], bp, BPT);
                }
                #pragma unroll
                for (int mt = 0; mt < 2; mt++) {
                    #pragma unroll
                    for (int nt = 0; nt < NTF; nt++) {
                        wmma::mma_sync(acc[mt][nt], af[mt], bf[nt], acc[mt][nt]);
                    }
                }
            } else {
                wmma::fragment<wmma::matrix_b, 16, 16, 16, __half, wmma::row_major> bf[NTF];
                #pragma unroll
                for (int nt = 0; nt < NTF; nt++) {
                    const __half* bp = &Bs[buf * BSZ + ks * BPN + wn * (BN / 2) + nt * 16];
                    wmma::load_matrix_sync(bf[nt], bp, BPN);
                }
                #pragma unroll
                for (int mt = 0; mt < 2; mt++) {
                    #pragma unroll
                    for (int nt = 0; nt < NTF; nt++) {
                        wmma::mma_sync(acc[mt][nt], af[mt], bf[nt], acc[mt][nt]);
                    }
                }
            }
        }
        __syncthreads();
    }

    /* epilogue: stage each 16x16 accumulator through smem (reuse As region) */
    float* stage = reinterpret_cast<float*>(smem) + warp * 16 * 20;
    const int er = lane >> 1;
    const int ec = (lane & 1) * 8;
    #pragma unroll
    for (int mt = 0; mt < 2; mt++) {
        #pragma unroll
        for (int nt = 0; nt < NTF; nt++) {
            wmma::store_matrix_sync(stage, acc[mt][nt], 20, wmma::mem_row_major);
            __syncwarp();
            const int row = brow + wm * 32 + mt * 16 + er;
            const int col = bcol + wn * (BN / 2) + nt * 16 + ec;
            float v[8];
            #pragma unroll
            for (int j = 0; j < 8; j++) v[j] = stage[er * 20 + ec + j];
            if (FLAGS & F_SCALE) {
                #pragma unroll
                for (int j = 0; j < 8; j++) v[j] *= scale;
            }
            if (FLAGS & F_BIAS) {
                #pragma unroll
                for (int j = 0; j < 8; j++) v[j] += bias[col + j];
            }
            if (FLAGS & F_GELU) {
                #pragma unroll
                for (int j = 0; j < 8; j++) v[j] = gelu_f(v[j]);
            }
            if (FLAGS & F_RES) {
                #pragma unroll
                for (int j = 0; j < 8; j++) v[j] += res[(long)row * ldr + col + j];
            }
            const long off = coff + (long)row * ldc + col;
            if (FLAGS & F_OUTF) {
                float4 f0;
                f0.x = v[0]; f0.y = v[1]; f0.z = v[2]; f0.w = v[3];
                float4 f1;
                f1.x = v[4]; f1.y = v[5]; f1.z = v[6]; f1.w = v[7];
                *reinterpret_cast<float4*>(&Cf[off]) = f0;
                *reinterpret_cast<float4*>(&Cf[off + 4]) = f1;
            }
            if (FLAGS & F_OUTH) {
                __half2* hp = reinterpret_cast<__half2*>(&Ch[off]);
                hp[0] = __floats2half2_rn(v[0], v[1]);
                hp[1] = __floats2half2_rn(v[2], v[3]);
                hp[2] = __floats2half2_rn(v[4], v[5]);
                hp[3] = __floats2half2_rn(v[6], v[7]);
            }
            __syncwarp();
        }
    }
}

extern "C" void kernel_launch(void* const* d_in, const int* in_sizes, int n_in,
                              void* d_out, int out_size) {
    const float* x       = (const float*)d_in[0];
    const int*   indices = (const int*)  d_in[1];
    const float* ln1_w   = (const float*)d_in[2];
    const float* ln1_b   = (const float*)d_in[3];
    const float* qkv_w   = (const float*)d_in[4];
    const float* qkv_b   = (const float*)d_in[5];
    const float* out_w   = (const float*)d_in[6];
    const float* out_b   = (const float*)d_in[7];
    const float* ln2_w   = (const float*)d_in[8];
    const float* ln2_b   = (const float*)d_in[9];
    const float* fc1_w   = (const float*)d_in[10];
    const float* fc1_b   = (const float*)d_in[11];
    const float* fc2_w   = (const float*)d_in[12];
    const float* fc2_b   = (const float*)d_in[13];
    const float* exp_w   = (const float*)d_in[14];
    const float* exp_b   = (const float*)d_in[15];

    float* out_final = (float*)d_out;
    float* attn      = out_final + (size_t)TOK * DIMC;

    void* p;
    cudaGetSymbolAddress(&p, g_xn_h);
    __half* xn_h = (__half*)p;
    cudaGetSymbolAddress(&p, g_qkv_h);
    __half* qkv_h = (__half*)p;
    cudaGetSymbolAddress(&p, g_attn_h);
    __half* attn_h = (__half*)p;
    cudaGetSymbolAddress(&p, g_ctx_h);
    __half* ctx_h = (__half*)p;
    cudaGetSymbolAddress(&p, g_x1);
    float* x1 = (float*)p;
    cudaGetSymbolAddress(&p, g_h_h);
    __half* h_h = (__half*)p;
    cudaGetSymbolAddress(&p, g_qkvw_h);
    __half* qkvw_h = (__half*)p;
    cudaGetSymbolAddress(&p, g_outw_h);
    __half* outw_h = (__half*)p;
    cudaGetSymbolAddress(&p, g_fc1w_h);
    __half* fc1w_h = (__half*)p;
    cudaGetSymbolAddress(&p, g_fc2w_h);
    __half* fc2w_h = (__half*)p;
    cudaGetSymbolAddress(&p, g_expw_h);
    __half* expw_h = (__half*)p;

    int n;
    n = DIMC * 3 * DIMC / 4;
    cvt_k<<<(n + 255) / 256, 256>>>(qkv_w, qkvw_h, n);
    n = DIMC * DIMC / 4;
    cvt_k<<<(n + 255) / 256, 256>>>(out_w, outw_h, n);
    n = DIMC * MLPC / 4;
    cvt_k<<<(n + 255) / 256, 256>>>(fc1_w, fc1w_h, n);
    n = MLPC * (DIMC - PART) / 4;
    cvt_k<<<(n + 255) / 256, 256>>>(fc2_w, fc2w_h, n);
    n = 8 * MLPC * PART / 4;
    cvt_k<<<(n + 255) / 256, 256>>>(exp_w, expw_h, n);

    layernorm_h_k<<<TOK, 256>>>(x, ln1_w, ln1_b, xn_h);

    hgemm<128, F_BIAS | F_OUTH, 0><<<dim3(24, 32, 1), 256>>>(
        xn_h, DIMC, qkvw_h, 3 * DIMC, nullptr, qkv_h, 3 * DIMC, DIMC,
        qkv_b, nullptr, 0, 0.f, nullptr, 0, 0,
        0L, 0L, 0L, 0L, 0L, 0L);

    hgemm<128, F_SCALE | F_OUTF, 1><<<dim3(4, 4, 128), 256>>>(
        qkv_h, 3 * DIMC, qkv_h + DIMC, 3 * DIMC, attn, nullptr, NSEQ, HD,
        nullptr, nullptr, 0, 0.03125f, nullptr, 0, 0,
        (long)NSEQ * 3 * DIMC, (long)HD,
        (long)NSEQ * 3 * DIMC, (long)HD,
        16L * NSEQ * NSEQ, (long)NSEQ * NSEQ);

    softmax_k<<<128 * NSEQ, 128>>>(attn, attn_h);

    hgemm<64, F_OUTH, 0><<<dim3(1, 4, 128), 256>>>(
        attn_h, NSEQ, qkv_h + 2 * DIMC, 3 * DIMC, nullptr, ctx_h, DIMC, NSEQ,
        nullptr, nullptr, 0, 0.f, nullptr, 0, 0,
        16L * NSEQ * NSEQ, (long)NSEQ * NSEQ,
        (long)NSEQ * 3 * DIMC, (long)HD,
        (long)NSEQ * DIMC, (long)HD);

    hgemm<128, F_BIAS | F_RES | F_OUTF, 0><<<dim3(8, 32, 1), 256>>>(
        ctx_h, DIMC, outw_h, DIMC, x1, nullptr, DIMC, DIMC,
        out_b, x, DIMC, 0.f, nullptr, 0, 0,
        0L, 0L, 0L, 0L, 0L, 0L);

    layernorm_h_k<<<TOK, 256>>>(x1, ln2_w, ln2_b, xn_h);

    hgemm<128, F_BIAS | F_GELU | F_OUTH, 0><<<dim3(32, 32, 1), 256>>>(
        xn_h, DIMC, fc1w_h, MLPC, nullptr, h_h, MLPC, DIMC,
        fc1_b, nullptr, 0, 0.f, nullptr, 0, 0,
        0L, 0L, 0L, 0L, 0L, 0L);

    hgemm<128, F_BIAS | F_RES | F_OUTF, 0><<<dim3(6, 32, 1), 256>>>(
        h_h, MLPC, fc2w_h, DIMC - PART, out_final, nullptr, DIMC, MLPC,
        fc2_b, x1, DIMC, 0.f, nullptr, 0, 0,
        0L, 0L, 0L, 0L, 0L, 0L);

    hgemm<128, F_BIAS | F_RES | F_OUTF | F_IDX, 0><<<dim3(2, 32, 1), 256>>>(
        h_h, MLPC, expw_h, PART, out_final + (DIMC - PART), nullptr, DIMC, MLPC,
        exp_b, x1 + (DIMC - PART), DIMC, 0.f,
        indices, (long)MLPC * PART, PART,
        0L, 0L, 0L, 0L, 0L, 0L);
}

// round 5
// speedup vs baseline: 5.3967x; 1.0224x over previous
#include <cuda_runtime.h>
#include <cuda_fp16.h>
#include <cuda_pipeline.h>
#include <mma.h>
#include <math.h>

#define TOK   4096
#define DIMC  1024
#define MLPC  4096
#define NSEQ  512
#define HD    64
#define PART  256

#define F_BIAS  1
#define F_GELU  2
#define F_RES   4
#define F_SCALE 8
#define F_OUTF  16
#define F_OUTH  32
#define F_IDX   64

using namespace nvcuda;

/* static device scratch */
__device__ __half g_xn_h [TOK * DIMC];
__device__ __half g_qkv_h[TOK * 3 * DIMC];
__device__ __half g_attn_h[(size_t)128 * NSEQ * NSEQ];
__device__ __half g_ctx_h[TOK * DIMC];
__device__ float  g_x1   [TOK * DIMC];
__device__ __half g_h_h  [TOK * MLPC];
__device__ __half g_qkvw_h[DIMC * 3 * DIMC];
__device__ __half g_outw_h[DIMC * DIMC];
__device__ __half g_fc1w_h[DIMC * MLPC];
__device__ __half g_fc2w_h[MLPC * (DIMC - PART)];
__device__ __half g_expw_h[8 * MLPC * PART];

__device__ __forceinline__ float gelu_f(float v) {
    return 0.5f * v * (1.0f + erff(v * 0.70710678118654752f));
}

/* fp32 to fp16 conversion */
__global__ void cvt_k(const float* __restrict__ in, __half* __restrict__ out, int n4) {
    int i = blockIdx.x * blockDim.x + threadIdx.x;
    if (i < n4) {
        float4 v = reinterpret_cast<const float4*>(in)[i];
        reinterpret_cast<__half2*>(out)[i * 2 + 0] = __floats2half2_rn(v.x, v.y);
        reinterpret_cast<__half2*>(out)[i * 2 + 1] = __floats2half2_rn(v.z, v.w);
    }
}

/* layernorm fp32 in, fp16 out */
__global__ void layernorm_h_k(const float* __restrict__ x,
                              const float* __restrict__ w,
                              const float* __restrict__ b,
                              __half* __restrict__ out) {
    int row = blockIdx.x;
    int t = threadIdx.x;
    float4 v = reinterpret_cast<const float4*>(x + (size_t)row * DIMC)[t];
    float s  = v.x + v.y + v.z + v.w;
    float sq = v.x * v.x + v.y * v.y + v.z * v.z + v.w * v.w;
    #pragma unroll
    for (int o = 16; o > 0; o >>= 1) {
        s  += __shfl_down_sync(0xffffffffu, s,  o);
        sq += __shfl_down_sync(0xffffffffu, sq, o);
    }
    __shared__ float ss[8];
    __shared__ float sq2[8];
    __shared__ float mean_s;
    __shared__ float rstd_s;
    int lane = t & 31;
    int wp = t >> 5;
    if (lane == 0) { ss[wp] = s; sq2[wp] = sq; }
    __syncthreads();
    if (t == 0) {
        float S = 0.f;
        float Q = 0.f;
        #pragma unroll
        for (int i = 0; i < 8; i++) { S += ss[i]; Q += sq2[i]; }
        float m = S * (1.0f / DIMC);
        mean_s = m;
        rstd_s = rsqrtf(Q * (1.0f / DIMC) - m * m + 1e-5f);
    }
    __syncthreads();
    float m = mean_s;
    float r = rstd_s;
    float4 wv = reinterpret_cast<const float4*>(w)[t];
    float4 bv = reinterpret_cast<const float4*>(b)[t];
    float o0 = (v.x - m) * r * wv.x + bv.x;
    float o1 = (v.y - m) * r * wv.y + bv.y;
    float o2 = (v.z - m) * r * wv.z + bv.z;
    float o3 = (v.w - m) * r * wv.w + bv.w;
    __half2* op = reinterpret_cast<__half2*>(out + (size_t)row * DIMC);
    op[t * 2 + 0] = __floats2half2_rn(o0, o1);
    op[t * 2 + 1] = __floats2half2_rn(o2, o3);
}

/* softmax: fp32 in-place plus fp16 copy */
__global__ void softmax_k(float* __restrict__ attn, __half* __restrict__ attn_h) {
    size_t row = blockIdx.x;
    float4* p = reinterpret_cast<float4*>(attn + row * NSEQ);
    int t = threadIdx.x;
    float4 v = p[t];
    float m = fmaxf(fmaxf(v.x, v.y), fmaxf(v.z, v.w));
    #pragma unroll
    for (int o = 16; o > 0; o >>= 1) m = fmaxf(m, __shfl_xor_sync(0xffffffffu, m, o));
    __shared__ float sm[4];
    __shared__ float ssum[4];
    int lane = t & 31;
    int wp = t >> 5;
    if (lane == 0) sm[wp] = m;
    __syncthreads();
    m = fmaxf(fmaxf(sm[0], sm[1]), fmaxf(sm[2], sm[3]));
    float4 e;
    e.x = expf(v.x - m);
    e.y = expf(v.y - m);
    e.z = expf(v.z - m);
    e.w = expf(v.w - m);
    float s = e.x + e.y + e.z + e.w;
    #pragma unroll
    for (int o = 16; o > 0; o >>= 1) s += __shfl_xor_sync(0xffffffffu, s, o);
    if (lane == 0) ssum[wp] = s;
    __syncthreads();
    s = ssum[0] + ssum[1] + ssum[2] + ssum[3];
    float inv = 1.0f / s;
    e.x *= inv;
    e.y *= inv;
    e.z *= inv;
    e.w *= inv;
    p[t] = e;
    __half2* hp = reinterpret_cast<__half2*>(attn_h + row * NSEQ);
    hp[t * 2 + 0] = __floats2half2_rn(e.x, e.y);
    hp[t * 2 + 1] = __floats2half2_rn(e.z, e.w);
}

/* one pipeline stage load: A tile 128x32, B tile (NN: 32xBN, NT: BNx32) */
template<int BN, int BT>
__device__ __forceinline__ void load_stage(const __half* A, int lda,
                                           const __half* B, int ldb,
                                           int brow, int bcol, int k0,
                                           __half* As, __half* Bs, int tid) {
    const int lr = tid >> 1;
    const int lc = (tid & 1) * 16;
    const int AP  = 40;
    const int BPN = BN + 8;
    const int BPT = 40;
    const __half* ga = A + (long)(brow + lr) * lda + k0 + lc;
    __pipeline_memcpy_async(&As[lr * AP + lc], ga, 16);
    __pipeline_memcpy_async(&As[lr * AP + lc + 8], ga + 8, 16);
    if (BT) {
        if (lr < BN) {
            const __half* gb = B + (long)(bcol + lr) * ldb + k0 + lc;
            __pipeline_memcpy_async(&Bs[lr * BPT + lc], gb, 16);
            __pipeline_memcpy_async(&Bs[lr * BPT + lc + 8], gb + 8, 16);
        }
    } else {
        const int CH = BN / 8;
        #pragma unroll
        for (int q = 0; q < (32 * CH + 255) / 256; q++) {
            const int idx = tid + q * 256;
            if (idx < 32 * CH) {
                const int r = idx / CH;
                const int c = idx % CH;
                __pipeline_memcpy_async(&Bs[r * BPN + c * 8],
                                        B + (long)(k0 + r) * ldb + bcol + c * 8, 16);
            }
        }
    }
}

/*
 * WMMA tensor-core GEMM. Block tile 128 x BN, K-step 32, 3-stage cp.async
 * pipeline in dynamic shared memory. 8 warps as 4(m) x 2(n): each warp owns
 * 32 x BN/2. BT=1 means B is [N,K] row-major (C = A by B-T). Batched over
 * blockIdx.z decomposed as (z>>4, z&15) with explicit strides.
 */
template<int BN, int FLAGS, int BT>
__global__ __launch_bounds__(256, 2)
void hgemm(const __half* __restrict__ A, int lda,
           const __half* __restrict__ B, int ldb,
           float* __restrict__ Cf, __half* __restrict__ Ch, int ldc,
           int K,
           const float* __restrict__ bias,
           const float* __restrict__ res, int ldr,
           float scale,
           const int* __restrict__ indices, long wstride, int bstride,
           long za1, long za2, long zb1, long zb2, long zc1, long zc2)
{
    const int z = blockIdx.z;
    const int zb = z >> 4;
    const int zh = z & 15;
    A += (long)zb * za1 + (long)zh * za2;
    B += (long)zb * zb1 + (long)zh * zb2;
    const long coff = (long)zb * zc1 + (long)zh * zc2;
    if (FLAGS & F_IDX) {
        int idx = indices[blockIdx.y >> 2];
        B    += (long)idx * wstride;
        bias += (long)idx * bstride;
    }
    const int brow = blockIdx.y * 128;
    const int bcol = blockIdx.x * BN;

    constexpr int AP  = 40;
    constexpr int BPN = BN + 8;
    constexpr int BPT = 40;
    constexpr int ASZ = 128 * AP;
    constexpr int BSZ = BT ? (BN * BPT) : (32 * BPN);

    extern __shared__ __align__(16) char dyn[];
    __half* As = reinterpret_cast<__half*>(dyn);
    __half* Bs = As + 3 * ASZ;

    const int tid  = threadIdx.x;
    const int warp = tid >> 5;
    const int lane = tid & 31;
    const int wm = warp & 3;
    const int wn = warp >> 2;
    constexpr int NTF = BN / 32;

    wmma::fragment<wmma::accumulator, 16, 16, 16, float> acc[2][NTF];
    #pragma unroll
    for (int i = 0; i < 2; i++) {
        #pragma unroll
        for (int j = 0; j < NTF; j++) wmma::fill_fragment(acc[i][j], 0.0f);
    }

    const int iters = K >> 5;

    load_stage<BN, BT>(A, lda, B, ldb, brow, bcol, 0, As, Bs, tid);
    __pipeline_commit();
    if (iters > 1) {
        load_stage<BN, BT>(A, lda, B, ldb, brow, bcol, 32, As + ASZ, Bs + BSZ, tid);
        __pipeline_commit();
    }

    for (int it = 0; it < iters; ++it) {
        if (it + 1 < iters) {
            __pipeline_wait_prior(1);
        } else {
            __pipeline_wait_prior(0);
        }
        __syncthreads();
        if (it + 2 < iters) {
            const int ns = (it + 2) % 3;
            load_stage<BN, BT>(A, lda, B, ldb, brow, bcol, (it + 2) * 32,
                               As + ns * ASZ, Bs + ns * BSZ, tid);
            __pipeline_commit();
        }
        const int slot = it % 3;

        #pragma unroll
        for (int ks = 0; ks < 32; ks += 16) {
            wmma::fragment<wmma::matrix_a, 16, 16, 16, __half, wmma::row_major> af[2];
            #pragma unroll
            for (int mt = 0; mt < 2; mt++) {
                const __half* ap = &As[slot * ASZ + (wm * 32 + mt * 16) * AP + ks];
                wmma::load_matrix_sync(af[mt], ap, AP);
            }
            if (BT) {
                wmma::fragment<wmma::matrix_b, 16, 16, 16, __half, wmma::col_major> bf[NTF];
                #pragma unroll
                for (int nt = 0; nt < NTF; nt++) {
                    const __half* bp = &Bs[slot * BSZ + (wn * (BN / 2) + nt * 16) * BPT + ks];
                    wmma::load_matrix_sync(bf[nt], bp, BPT);
                }
                #pragma unroll
                for (int mt = 0; mt < 2; mt++) {
                    #pragma unroll
                    for (int nt = 0; nt < NTF; nt++) {
                        wmma::mma_sync(acc[mt][nt], af[mt], bf[nt], acc[mt][nt]);
                    }
                }
            } else {
                wmma::fragment<wmma::matrix_b, 16, 16, 16, __half, wmma::row_major> bf[NTF];
                #pragma unroll
                for (int nt = 0; nt < NTF; nt++) {
                    const __half* bp = &Bs[slot * BSZ + ks * BPN + wn * (BN / 2) + nt * 16];
                    wmma::load_matrix_sync(bf[nt], bp, BPN);
                }
                #pragma unroll
                for (int mt = 0; mt < 2; mt++) {
                    #pragma unroll
                    for (int nt = 0; nt < NTF; nt++) {
                        wmma::mma_sync(acc[mt][nt], af[mt], bf[nt], acc[mt][nt]);
                    }
                }
            }
        }
    }

    __syncthreads();

    /* epilogue: stage each 16x16 accumulator through smem */
    float* stage = reinterpret_cast<float*>(dyn) + warp * 16 * 20;
    const int er = lane >> 1;
    const int ec = (lane & 1) * 8;
    #pragma unroll
    for (int mt = 0; mt < 2; mt++) {
        #pragma unroll
        for (int nt = 0; nt < NTF; nt++) {
            wmma::store_matrix_sync(stage, acc[mt][nt], 20, wmma::mem_row_major);
            __syncwarp();
            const int row = brow + wm * 32 + mt * 16 + er;
            const int col = bcol + wn * (BN / 2) + nt * 16 + ec;
            float v[8];
            #pragma unroll
            for (int j = 0; j < 8; j++) v[j] = stage[er * 20 + ec + j];
            if (FLAGS & F_SCALE) {
                #pragma unroll
                for (int j = 0; j < 8; j++) v[j] *= scale;
            }
            if (FLAGS & F_BIAS) {
                #pragma unroll
                for (int j = 0; j < 8; j++) v[j] += bias[col + j];
            }
            if (FLAGS & F_GELU) {
                #pragma unroll
                for (int j = 0; j < 8; j++) v[j] = gelu_f(v[j]);
            }
            if (FLAGS & F_RES) {
                #pragma unroll
                for (int j = 0; j < 8; j++) v[j] += res[(long)row * ldr + col + j];
            }
            const long off = coff + (long)row * ldc + col;
            if (FLAGS & F_OUTF) {
                float4 f0;
                f0.x = v[0]; f0.y = v[1]; f0.z = v[2]; f0.w = v[3];
                float4 f1;
                f1.x = v[4]; f1.y = v[5]; f1.z = v[6]; f1.w = v[7];
                *reinterpret_cast<float4*>(&Cf[off]) = f0;
                *reinterpret_cast<float4*>(&Cf[off + 4]) = f1;
            }
            if (FLAGS & F_OUTH) {
                __half2* hp = reinterpret_cast<__half2*>(&Ch[off]);
                hp[0] = __floats2half2_rn(v[0], v[1]);
                hp[1] = __floats2half2_rn(v[2], v[3]);
                hp[2] = __floats2half2_rn(v[4], v[5]);
                hp[3] = __floats2half2_rn(v[6], v[7]);
            }
            __syncwarp();
        }
    }
}

/* dynamic smem byte counts per instantiation */
#define SMEM_NN128 (3 * (128 * 40 + 32 * 136) * 2)
#define SMEM_BT128 (3 * (128 * 40 + 128 * 40) * 2)
#define SMEM_NN64  (3 * (128 * 40 + 32 * 72) * 2)

extern "C" void kernel_launch(void* const* d_in, const int* in_sizes, int n_in,
                              void* d_out, int out_size) {
    const float* x       = (const float*)d_in[0];
    const int*   indices = (const int*)  d_in[1];
    const float* ln1_w   = (const float*)d_in[2];
    const float* ln1_b   = (const float*)d_in[3];
    const float* qkv_w   = (const float*)d_in[4];
    const float* qkv_b   = (const float*)d_in[5];
    const float* out_w   = (const float*)d_in[6];
    const float* out_b   = (const float*)d_in[7];
    const float* ln2_w   = (const float*)d_in[8];
    const float* ln2_b   = (const float*)d_in[9];
    const float* fc1_w   = (const float*)d_in[10];
    const float* fc1_b   = (const float*)d_in[11];
    const float* fc2_w   = (const float*)d_in[12];
    const float* fc2_b   = (const float*)d_in[13];
    const float* exp_w   = (const float*)d_in[14];
    const float* exp_b   = (const float*)d_in[15];

    float* out_final = (float*)d_out;
    float* attn      = out_final + (size_t)TOK * DIMC;

    void* p;
    cudaGetSymbolAddress(&p, g_xn_h);
    __half* xn_h = (__half*)p;
    cudaGetSymbolAddress(&p, g_qkv_h);
    __half* qkv_h = (__half*)p;
    cudaGetSymbolAddress(&p, g_attn_h);
    __half* attn_h = (__half*)p;
    cudaGetSymbolAddress(&p, g_ctx_h);
    __half* ctx_h = (__half*)p;
    cudaGetSymbolAddress(&p, g_x1);
    float* x1 = (float*)p;
    cudaGetSymbolAddress(&p, g_h_h);
    __half* h_h = (__half*)p;
    cudaGetSymbolAddress(&p, g_qkvw_h);
    __half* qkvw_h = (__half*)p;
    cudaGetSymbolAddress(&p, g_outw_h);
    __half* outw_h = (__half*)p;
    cudaGetSymbolAddress(&p, g_fc1w_h);
    __half* fc1w_h = (__half*)p;
    cudaGetSymbolAddress(&p, g_fc2w_h);
    __half* fc2w_h = (__half*)p;
    cudaGetSymbolAddress(&p, g_expw_h);
    __half* expw_h = (__half*)p;

    cudaFuncSetAttribute(hgemm<128, F_BIAS | F_OUTH, 0>,
                         cudaFuncAttributeMaxDynamicSharedMemorySize, SMEM_NN128);
    cudaFuncSetAttribute(hgemm<128, F_SCALE | F_OUTF, 1>,
                         cudaFuncAttributeMaxDynamicSharedMemorySize, SMEM_BT128);
    cudaFuncSetAttribute(hgemm<64, F_OUTH, 0>,
                         cudaFuncAttributeMaxDynamicSharedMemorySize, SMEM_NN64);
    cudaFuncSetAttribute(hgemm<128, F_BIAS | F_RES | F_OUTF, 0>,
                         cudaFuncAttributeMaxDynamicSharedMemorySize, SMEM_NN128);
    cudaFuncSetAttribute(hgemm<128, F_BIAS | F_GELU | F_OUTH, 0>,
                         cudaFuncAttributeMaxDynamicSharedMemorySize, SMEM_NN128);
    cudaFuncSetAttribute(hgemm<128, F_BIAS | F_RES | F_OUTF | F_IDX, 0>,
                         cudaFuncAttributeMaxDynamicSharedMemorySize, SMEM_NN128);

    int n;
    n = DIMC * 3 * DIMC / 4;
    cvt_k<<<(n + 255) / 256, 256>>>(qkv_w, qkvw_h, n);
    n = DIMC * DIMC / 4;
    cvt_k<<<(n + 255) / 256, 256>>>(out_w, outw_h, n);
    n = DIMC * MLPC / 4;
    cvt_k<<<(n + 255) / 256, 256>>>(fc1_w, fc1w_h, n);
    n = MLPC * (DIMC - PART) / 4;
    cvt_k<<<(n + 255) / 256, 256>>>(fc2_w, fc2w_h, n);
    n = 8 * MLPC * PART / 4;
    cvt_k<<<(n + 255) / 256, 256>>>(exp_w, expw_h, n);

    layernorm_h_k<<<TOK, 256>>>(x, ln1_w, ln1_b, xn_h);

    hgemm<128, F_BIAS | F_OUTH, 0><<<dim3(24, 32, 1), 256, SMEM_NN128>>>(
        xn_h, DIMC, qkvw_h, 3 * DIMC, nullptr, qkv_h, 3 * DIMC, DIMC,
        qkv_b, nullptr, 0, 0.f, nullptr, 0, 0,
        0L, 0L, 0L, 0L, 0L, 0L);

    hgemm<128, F_SCALE | F_OUTF, 1><<<dim3(4, 4, 128), 256, SMEM_BT128>>>(
        qkv_h, 3 * DIMC, qkv_h + DIMC, 3 * DIMC, attn, nullptr, NSEQ, HD,
        nullptr, nullptr, 0, 0.03125f, nullptr, 0, 0,
        (long)NSEQ * 3 * DIMC, (long)HD,
        (long)NSEQ * 3 * DIMC, (long)HD,
        16L * NSEQ * NSEQ, (long)NSEQ * NSEQ);

    softmax_k<<<128 * NSEQ, 128>>>(attn, attn_h);

    hgemm<64, F_OUTH, 0><<<dim3(1, 4, 128), 256, SMEM_NN64>>>(
        attn_h, NSEQ, qkv_h + 2 * DIMC, 3 * DIMC, nullptr, ctx_h, DIMC, NSEQ,
        nullptr, nullptr, 0, 0.f, nullptr, 0, 0,
        16L * NSEQ * NSEQ, (long)NSEQ * NSEQ,
        (long)NSEQ * 3 * DIMC, (long)HD,
        (long)NSEQ * DIMC, (long)HD);

    hgemm<128, F_BIAS | F_RES | F_OUTF, 0><<<dim3(8, 32, 1), 256, SMEM_NN128>>>(
        ctx_h, DIMC, outw_h, DIMC, x1, nullptr, DIMC, DIMC,
        out_b, x, DIMC, 0.f, nullptr, 0, 0,
        0L, 0L, 0L, 0L, 0L, 0L);

    layernorm_h_k<<<TOK, 256>>>(x1, ln2_w, ln2_b, xn_h);

    hgemm<128, F_BIAS | F_GELU | F_OUTH, 0><<<dim3(32, 32, 1), 256, SMEM_NN128>>>(
        xn_h, DIMC, fc1w_h, MLPC, nullptr, h_h, MLPC, DIMC,
        fc1_b, nullptr, 0, 0.f, nullptr, 0, 0,
        0L, 0L, 0L, 0L, 0L, 0L);

    hgemm<128, F_BIAS | F_RES | F_OUTF, 0><<<dim3(6, 32, 1), 256, SMEM_NN128>>>(
        h_h, MLPC, fc2w_h, DIMC - PART, out_final, nullptr, DIMC, MLPC,
        fc2_b, x1, DIMC, 0.f, nullptr, 0, 0,
        0L, 0L, 0L, 0L, 0L, 0L);

    hgemm<128, F_BIAS | F_RES | F_OUTF | F_IDX, 0><<<dim3(2, 32, 1), 256, SMEM_NN128>>>(
        h_h, MLPC, expw_h, PART, out_final + (DIMC - PART), nullptr, DIMC, MLPC,
        exp_b, x1 + (DIMC - PART), DIMC, 0.f,
        indices, (long)MLPC * PART, PART,
        0L, 0L, 0L, 0L, 0L, 0L);
}